// round 3
// baseline (speedup 1.0000x reference)
#include <cuda_runtime.h>

// Problem constants
#define B_    256
#define N_    128
#define EB_   5
#define NA_   64
#define DIM_  512
#define NIT_  3
#define MROWS (B_ * N_)   // 32768

// Scratch (static device globals — no runtime allocation allowed)
__device__ float g_asum[B_ * N_ * N_];     // [B, N, N]  summed edge channels
__device__ float g_h[MROWS * DIM_];        // hidden state
__device__ float g_t[MROWS * DIM_];        // h + agg

// ---------------------------------------------------------------------------
// K0: Asum[b,n,m] = sum_{e=1..4} adj[b,n,m,e]   (channel 0 dropped)
// ---------------------------------------------------------------------------
__global__ void asum_kernel(const float* __restrict__ adj) {
    int i = blockIdx.x * blockDim.x + threadIdx.x;   // 0 .. B*N*N-1, exact grid
    const float* p = adj + (long long)i * EB_;
    g_asum[i] = p[1] + p[2] + p[3] + p[4];
}

// ---------------------------------------------------------------------------
// Generic tiled SGEMM: D = epilogue( A[M,K] @ B[K,N] )
//   - bias      (optional, per-column) added
//   - Cadd      (optional, same shape as D) added elementwise
//   - relu      applied if flag set
//   - bStride   if nonzero: B is batched, effective B = B + blockIdx.y*bStride
//               (valid because BM == rows-per-batch == 128 for the agg GEMM;
//                A is always indexed by GLOBAL row, which is already correct
//                for the block-diagonal Asum layout)
// Tile: BM=128, BN=128, BK=16, 256 threads, 8x8 outputs per thread.
// ---------------------------------------------------------------------------
#define BM 128
#define BN 128
#define BK 16

__global__ __launch_bounds__(256, 2)
void sgemm128(const float* __restrict__ A, const float* __restrict__ B,
              const float* __restrict__ bias, const float* __restrict__ Cadd,
              float* __restrict__ D, int M, int N, int K,
              long long bStride, int relu)
{
    __shared__ float As[BK][BM];   // transposed A tile (k-major)
    __shared__ float Bs[BK][BN];

    const int tid = threadIdx.x;
    const int bm  = blockIdx.y;
    const int bn  = blockIdx.x;

    const float* Bp = B + (long long)bm * bStride;

    // Output mapping: 8 warps as 4(m) x 2(n); lane as 4(m) x 8(n); 8x8 per thread
    const int warp = tid >> 5;
    const int lane = tid & 31;
    const int tm = (warp >> 1) * 32 + (lane >> 3) * 8;   // 0..120
    const int tn = (warp & 1)  * 64 + (lane & 7)  * 8;   // 0..120

    // Global-load mapping
    const int arow = tid >> 1;          // 0..127
    const int acol = (tid & 1) * 8;     // 0 or 8
    const int brow = tid >> 4;          // 0..15
    const int bcol = (tid & 15) * 8;    // 0..120

    float acc[8][8];
    #pragma unroll
    for (int i = 0; i < 8; i++)
        #pragma unroll
        for (int j = 0; j < 8; j++)
            acc[i][j] = 0.0f;

    for (int k0 = 0; k0 < K; k0 += BK) {
        // --- load A tile (BM x BK), store transposed into As[k][m] ---
        const float* ap = A + ((long long)(bm * BM + arow)) * K + k0 + acol;
        float4 a0 = *(const float4*)(ap);
        float4 a1 = *(const float4*)(ap + 4);
        As[acol + 0][arow] = a0.x;
        As[acol + 1][arow] = a0.y;
        As[acol + 2][arow] = a0.z;
        As[acol + 3][arow] = a0.w;
        As[acol + 4][arow] = a1.x;
        As[acol + 5][arow] = a1.y;
        As[acol + 6][arow] = a1.z;
        As[acol + 7][arow] = a1.w;

        // --- load B tile (BK x BN) ---
        const float* bp = Bp + ((long long)(k0 + brow)) * N + bn * BN + bcol;
        *(float4*)&Bs[brow][bcol]     = *(const float4*)(bp);
        *(float4*)&Bs[brow][bcol + 4] = *(const float4*)(bp + 4);

        __syncthreads();

        #pragma unroll
        for (int kk = 0; kk < BK; kk++) {
            float ar[8], br[8];
            *(float4*)&ar[0] = *(const float4*)&As[kk][tm];
            *(float4*)&ar[4] = *(const float4*)&As[kk][tm + 4];
            *(float4*)&br[0] = *(const float4*)&Bs[kk][tn];
            *(float4*)&br[4] = *(const float4*)&Bs[kk][tn + 4];
            #pragma unroll
            for (int i = 0; i < 8; i++)
                #pragma unroll
                for (int j = 0; j < 8; j++)
                    acc[i][j] += ar[i] * br[j];
        }
        __syncthreads();
    }

    // --- epilogue ---
    float bv[8];
    if (bias) {
        *(float4*)&bv[0] = *(const float4*)(bias + bn * BN + tn);
        *(float4*)&bv[4] = *(const float4*)(bias + bn * BN + tn + 4);
    } else {
        #pragma unroll
        for (int j = 0; j < 8; j++) bv[j] = 0.0f;
    }

    #pragma unroll
    for (int i = 0; i < 8; i++) {
        const long long gm = (long long)(bm * BM + tm + i);
        float* drow = D + gm * N + bn * BN + tn;
        float v[8];
        #pragma unroll
        for (int j = 0; j < 8; j++) v[j] = acc[i][j] + bv[j];
        if (Cadd) {
            const float* crow = Cadd + gm * N + bn * BN + tn;
            float4 c0 = *(const float4*)(crow);
            float4 c1 = *(const float4*)(crow + 4);
            v[0] += c0.x; v[1] += c0.y; v[2] += c0.z; v[3] += c0.w;
            v[4] += c1.x; v[5] += c1.y; v[6] += c1.z; v[7] += c1.w;
        }
        if (relu) {
            #pragma unroll
            for (int j = 0; j < 8; j++) v[j] = fmaxf(v[j], 0.0f);
        }
        float4 s0, s1;
        s0.x = v[0]; s0.y = v[1]; s0.z = v[2]; s0.w = v[3];
        s1.x = v[4]; s1.y = v[5]; s1.z = v[6]; s1.w = v[7];
        *(float4*)(drow)     = s0;
        *(float4*)(drow + 4) = s1;
    }
}

// ---------------------------------------------------------------------------
// K4: graph_repr = mean_n h;  logit = graph_repr @ W_out + b_out
// out layout: [ logit(256) | graph_repr(256*512) ]
// ---------------------------------------------------------------------------
__global__ void finalize_kernel(const float* __restrict__ h,
                                const float* __restrict__ W_out,
                                const float* __restrict__ b_out,
                                float* __restrict__ out)
{
    const int b   = blockIdx.x;
    const int tid = threadIdx.x;   // 256 threads, each owns 2 columns
    const float* base = h + (long long)b * N_ * DIM_;

    float s0 = 0.0f, s1 = 0.0f;
    #pragma unroll 4
    for (int n = 0; n < N_; n++) {
        const float* row = base + (long long)n * DIM_;
        s0 += row[tid];
        s1 += row[tid + 256];
    }
    const float g0 = s0 * (1.0f / (float)N_);
    const float g1 = s1 * (1.0f / (float)N_);

    out[B_ + b * DIM_ + tid]       = g0;
    out[B_ + b * DIM_ + tid + 256] = g1;

    __shared__ float red[256];
    red[tid] = g0 * W_out[tid] + g1 * W_out[tid + 256];
    __syncthreads();
    for (int s = 128; s > 0; s >>= 1) {
        if (tid < s) red[tid] += red[tid + s];
        __syncthreads();
    }
    if (tid == 0) out[b] = red[0] + b_out[0];
}

// ---------------------------------------------------------------------------
// launch
// ---------------------------------------------------------------------------
extern "C" void kernel_launch(void* const* d_in, const int* in_sizes, int n_in,
                              void* d_out, int out_size)
{
    const float* adj      = (const float*)d_in[0];
    // d_in[1] = hidden (unused by forward)
    const float* node     = (const float*)d_in[2];
    const float* W_embed  = (const float*)d_in[3];
    const float* b_embed  = (const float*)d_in[4];
    const float* W_layers = (const float*)d_in[5];
    const float* b_layers = (const float*)d_in[6];
    const float* W_out    = (const float*)d_in[7];
    const float* b_out    = (const float*)d_in[8];
    float* out = (float*)d_out;

    float *asum, *h, *t;
    cudaGetSymbolAddress((void**)&asum, g_asum);
    cudaGetSymbolAddress((void**)&h,    g_h);
    cudaGetSymbolAddress((void**)&t,    g_t);

    // K0: fold edge channels once (iteration-invariant)
    asum_kernel<<<(B_ * N_ * N_) / 256, 256>>>(adj);

    dim3 grid(DIM_ / BN, MROWS / BM);   // (4, 256)

    // embed: h = node @ W_embed + b_embed
    sgemm128<<<grid, 256>>>(node, W_embed, b_embed, nullptr, h,
                            MROWS, DIM_, NA_, 0LL, 0);

    for (int i = 0; i < NIT_; i++) {
        // t = Asum[b] @ h[b] + h      (batched: B offset per 128-row block)
        sgemm128<<<grid, 256>>>(asum, h, nullptr, h, t,
                                MROWS, DIM_, N_, (long long)N_ * DIM_, 0);
        // h = relu(t @ W_i + b_i)
        sgemm128<<<grid, 256>>>(t, W_layers + (long long)i * DIM_ * DIM_,
                                b_layers + i * DIM_, nullptr, h,
                                MROWS, DIM_, DIM_, 0LL, 1);
    }

    // mean + readout head; writes all out_size elements
    finalize_kernel<<<B_, 256>>>(h, W_out, b_out, out);
}

// round 4
// speedup vs baseline: 1.1968x; 1.1968x over previous
#include <cuda_runtime.h>

// Problem constants
#define B_    256
#define N_    128
#define EB_   5
#define NA_   64
#define DIM_  512
#define NIT_  3
#define MROWS (B_ * N_)   // 32768

// Scratch (static device globals — no runtime allocation allowed)
__device__ float g_asum[B_ * N_ * N_];     // [B, N, N]  summed edge channels
__device__ float g_h[MROWS * DIM_];        // hidden state
__device__ float g_t[MROWS * DIM_];        // h + agg

// ---------------------------------------------------------------------------
// K0: Asum[b,n,m] = sum_{e=1..4} adj[b,n,m,e]   (channel 0 dropped)
// ---------------------------------------------------------------------------
__global__ void asum_kernel(const float* __restrict__ adj) {
    int i = blockIdx.x * blockDim.x + threadIdx.x;
    const float* p = adj + (long long)i * EB_;
    g_asum[i] = p[1] + p[2] + p[3] + p[4];
}

// ---------------------------------------------------------------------------
// TF32 helpers
// ---------------------------------------------------------------------------
__device__ __forceinline__ unsigned f2tf(float x) {
    unsigned y;
    asm("cvt.rna.tf32.f32 %0, %1;" : "=r"(y) : "f"(x));
    return y;
}

__device__ __forceinline__ void mma8(float* c, const unsigned* a, const unsigned* b) {
    asm volatile(
        "mma.sync.aligned.m16n8k8.row.col.f32.tf32.tf32.f32 "
        "{%0,%1,%2,%3}, {%4,%5,%6,%7}, {%8,%9}, {%0,%1,%2,%3};"
        : "+f"(c[0]), "+f"(c[1]), "+f"(c[2]), "+f"(c[3])
        : "r"(a[0]), "r"(a[1]), "r"(a[2]), "r"(a[3]), "r"(b[0]), "r"(b[1]));
}

// ---------------------------------------------------------------------------
// 3xTF32 GEMM: D = epilogue( A[M,K] @ B[K,N] )  with near-fp32 precision.
//   A split as a_hi + a_lo (both tf32); D += a_hi*b_hi + a_lo*b_hi + a_hi*b_lo.
//   bias (per-col), Cadd (elementwise), relu optional.
//   bStride: batched-B offset per 128-row block (agg GEMM uses it).
// Tile: BM=128, BN=128, BK=16, 256 threads (8 warps = 2m x 4n, 64x32/warp).
// Smem: stride 136 -> k-row adds 8 banks; the 4-k x 8-consecutive fragment
// read pattern covers all 32 banks (conflict-free LDS).
// ---------------------------------------------------------------------------
#define BKT  16
#define LDA  136
#define ABUF (BKT * LDA)          // 2176 uints per buffer
#define SMEM_BYTES (8 * ABUF * 4) // 69632 B

__global__ __launch_bounds__(256)
void tgemm(const float* __restrict__ A, const float* __restrict__ Bm,
           const float* __restrict__ bias, const float* __restrict__ Cadd,
           float* __restrict__ D, int M, int N, int K,
           long long bStride, int relu)
{
    extern __shared__ unsigned sm[];
    unsigned* SAh = sm;                 // [2][BKT][LDA]
    unsigned* SAl = sm + 2 * ABUF;
    unsigned* SBh = sm + 4 * ABUF;
    unsigned* SBl = sm + 6 * ABUF;

    const int tid  = threadIdx.x;
    const int bm   = blockIdx.y;
    const int bn   = blockIdx.x;
    const int warp = tid >> 5;
    const int lane = tid & 31;
    const int wm = (warp >> 2) * 64;    // warp m-offset (0 or 64)
    const int wn = (warp & 3) * 32;     // warp n-offset (0..96)

    const float* Bp = Bm + (long long)bm * bStride;

    // loader mapping
    const int a_r = tid >> 1;           // 0..127 (m)
    const int a_c = (tid & 1) * 8;      // 0 or 8 (k)
    const int b_r = tid >> 4;           // 0..15  (k)
    const int b_c = (tid & 15) * 8;     // 0..120 (n)

    const float* apBase = A  + (long long)(bm * 128 + a_r) * K + a_c;
    const float* bpBase = Bp + (long long)b_r * N + bn * 128 + b_c;

    float acc[4][4][4];
    #pragma unroll
    for (int i = 0; i < 4; i++)
        #pragma unroll
        for (int j = 0; j < 4; j++)
            #pragma unroll
            for (int q = 0; q < 4; q++) acc[i][j][q] = 0.0f;

    float4 ra0, ra1, rb0, rb1;   // staging regs for next tile

    auto sts = [&](int b_) {
        unsigned* sa_h = SAh + b_ * ABUF;
        unsigned* sa_l = SAl + b_ * ABUF;
        unsigned* sb_h = SBh + b_ * ABUF;
        unsigned* sb_l = SBl + b_ * ABUF;
        float av[8] = {ra0.x, ra0.y, ra0.z, ra0.w, ra1.x, ra1.y, ra1.z, ra1.w};
        #pragma unroll
        for (int j = 0; j < 8; j++) {
            unsigned h = f2tf(av[j]);
            unsigned l = f2tf(av[j] - __uint_as_float(h));
            sa_h[(a_c + j) * LDA + a_r] = h;
            sa_l[(a_c + j) * LDA + a_r] = l;
        }
        float bv[8] = {rb0.x, rb0.y, rb0.z, rb0.w, rb1.x, rb1.y, rb1.z, rb1.w};
        unsigned bh[8], bl[8];
        #pragma unroll
        for (int j = 0; j < 8; j++) {
            bh[j] = f2tf(bv[j]);
            bl[j] = f2tf(bv[j] - __uint_as_float(bh[j]));
        }
        *(uint4*)&sb_h[b_r * LDA + b_c]     = make_uint4(bh[0], bh[1], bh[2], bh[3]);
        *(uint4*)&sb_h[b_r * LDA + b_c + 4] = make_uint4(bh[4], bh[5], bh[6], bh[7]);
        *(uint4*)&sb_l[b_r * LDA + b_c]     = make_uint4(bl[0], bl[1], bl[2], bl[3]);
        *(uint4*)&sb_l[b_r * LDA + b_c + 4] = make_uint4(bl[4], bl[5], bl[6], bl[7]);
    };

    // prologue: load + store step 0
    ra0 = *(const float4*)(apBase);
    ra1 = *(const float4*)(apBase + 4);
    rb0 = *(const float4*)(bpBase);
    rb1 = *(const float4*)(bpBase + 4);
    sts(0);
    __syncthreads();

    const int steps = K / BKT;
    int buf = 0;

    for (int s = 0; s < steps; s++) {
        // prefetch next K-slab into registers (overlaps with compute)
        if (s + 1 < steps) {
            const float* ap = apBase + (s + 1) * BKT;
            const float* bp = bpBase + (long long)(s + 1) * BKT * N;
            ra0 = *(const float4*)(ap);
            ra1 = *(const float4*)(ap + 4);
            rb0 = *(const float4*)(bp);
            rb1 = *(const float4*)(bp + 4);
        }

        unsigned* sa_h = SAh + buf * ABUF;
        unsigned* sa_l = SAl + buf * ABUF;
        unsigned* sb_h = SBh + buf * ABUF;
        unsigned* sb_l = SBl + buf * ABUF;

        #pragma unroll
        for (int kb = 0; kb < 2; kb++) {
            const int k0 = kb * 8;
            unsigned ah[4][4], al[4][4], bh[4][2], bl[4][2];

            const int ak = (k0 + (lane & 3)) * LDA;
            const int am = wm + (lane >> 2);
            #pragma unroll
            for (int mt = 0; mt < 4; mt++) {
                const int idx = ak + am + mt * 16;
                ah[mt][0] = sa_h[idx];
                ah[mt][1] = sa_h[idx + 8];
                ah[mt][2] = sa_h[idx + 4 * LDA];
                ah[mt][3] = sa_h[idx + 4 * LDA + 8];
                al[mt][0] = sa_l[idx];
                al[mt][1] = sa_l[idx + 8];
                al[mt][2] = sa_l[idx + 4 * LDA];
                al[mt][3] = sa_l[idx + 4 * LDA + 8];
            }
            const int bnn = wn + (lane >> 2);
            #pragma unroll
            for (int nt = 0; nt < 4; nt++) {
                const int idx = ak + bnn + nt * 8;
                bh[nt][0] = sb_h[idx];
                bh[nt][1] = sb_h[idx + 4 * LDA];
                bl[nt][0] = sb_l[idx];
                bl[nt][1] = sb_l[idx + 4 * LDA];
            }

            #pragma unroll
            for (int mt = 0; mt < 4; mt++)
                #pragma unroll
                for (int nt = 0; nt < 4; nt++) {
                    mma8(acc[mt][nt], ah[mt], bh[nt]);
                    mma8(acc[mt][nt], al[mt], bh[nt]);
                    mma8(acc[mt][nt], ah[mt], bl[nt]);
                }
        }

        if (s + 1 < steps) sts(buf ^ 1);
        __syncthreads();
        buf ^= 1;
    }

    // --- epilogue ---
    // C frag mapping: c0:(r, c) c1:(r, c+1) c2:(r+8, c) c3:(r+8, c+1)
    // with r = wm + mt*16 + lane/4, c = wn + nt*8 + 2*(lane&3)
    float2 bv[4];
    #pragma unroll
    for (int nt = 0; nt < 4; nt++) {
        if (bias) {
            const int c = bn * 128 + wn + nt * 8 + 2 * (lane & 3);
            bv[nt] = *(const float2*)(bias + c);
        } else {
            bv[nt] = make_float2(0.0f, 0.0f);
        }
    }

    #pragma unroll
    for (int mt = 0; mt < 4; mt++) {
        const long long r0 = (long long)(bm * 128 + wm + mt * 16 + (lane >> 2));
        const long long r1 = r0 + 8;
        #pragma unroll
        for (int nt = 0; nt < 4; nt++) {
            const int c = bn * 128 + wn + nt * 8 + 2 * (lane & 3);
            float v0 = acc[mt][nt][0] + bv[nt].x;
            float v1 = acc[mt][nt][1] + bv[nt].y;
            float v2 = acc[mt][nt][2] + bv[nt].x;
            float v3 = acc[mt][nt][3] + bv[nt].y;
            if (Cadd) {
                float2 c0 = *(const float2*)(Cadd + r0 * N + c);
                float2 c1 = *(const float2*)(Cadd + r1 * N + c);
                v0 += c0.x; v1 += c0.y; v2 += c1.x; v3 += c1.y;
            }
            if (relu) {
                v0 = fmaxf(v0, 0.0f); v1 = fmaxf(v1, 0.0f);
                v2 = fmaxf(v2, 0.0f); v3 = fmaxf(v3, 0.0f);
            }
            *(float2*)(D + r0 * N + c) = make_float2(v0, v1);
            *(float2*)(D + r1 * N + c) = make_float2(v2, v3);
        }
    }
}

// ---------------------------------------------------------------------------
// K4: graph_repr = mean_n h;  logit = graph_repr @ W_out + b_out
// out layout: [ logit(256) | graph_repr(256*512) ]
// ---------------------------------------------------------------------------
__global__ void finalize_kernel(const float* __restrict__ h,
                                const float* __restrict__ W_out,
                                const float* __restrict__ b_out,
                                float* __restrict__ out)
{
    const int b   = blockIdx.x;
    const int tid = threadIdx.x;
    const float* base = h + (long long)b * N_ * DIM_;

    float s0 = 0.0f, s1 = 0.0f;
    #pragma unroll 4
    for (int n = 0; n < N_; n++) {
        const float* row = base + (long long)n * DIM_;
        s0 += row[tid];
        s1 += row[tid + 256];
    }
    const float g0 = s0 * (1.0f / (float)N_);
    const float g1 = s1 * (1.0f / (float)N_);

    out[B_ + b * DIM_ + tid]       = g0;
    out[B_ + b * DIM_ + tid + 256] = g1;

    __shared__ float red[256];
    red[tid] = g0 * W_out[tid] + g1 * W_out[tid + 256];
    __syncthreads();
    for (int s = 128; s > 0; s >>= 1) {
        if (tid < s) red[tid] += red[tid + s];
        __syncthreads();
    }
    if (tid == 0) out[b] = red[0] + b_out[0];
}

// ---------------------------------------------------------------------------
// launch
// ---------------------------------------------------------------------------
extern "C" void kernel_launch(void* const* d_in, const int* in_sizes, int n_in,
                              void* d_out, int out_size)
{
    const float* adj      = (const float*)d_in[0];
    // d_in[1] = hidden (unused by forward)
    const float* node     = (const float*)d_in[2];
    const float* W_embed  = (const float*)d_in[3];
    const float* b_embed  = (const float*)d_in[4];
    const float* W_layers = (const float*)d_in[5];
    const float* b_layers = (const float*)d_in[6];
    const float* W_out    = (const float*)d_in[7];
    const float* b_out    = (const float*)d_in[8];
    float* out = (float*)d_out;

    float *asum, *h, *t;
    cudaGetSymbolAddress((void**)&asum, g_asum);
    cudaGetSymbolAddress((void**)&h,    g_h);
    cudaGetSymbolAddress((void**)&t,    g_t);

    cudaFuncSetAttribute(tgemm, cudaFuncAttributeMaxDynamicSharedMemorySize,
                         SMEM_BYTES);

    // K0: fold edge channels once (iteration-invariant)
    asum_kernel<<<(B_ * N_ * N_) / 256, 256>>>(adj);

    dim3 grid(DIM_ / 128, MROWS / 128);   // (4, 256)

    // embed: h = node @ W_embed + b_embed   (K=64)
    tgemm<<<grid, 256, SMEM_BYTES>>>(node, W_embed, b_embed, nullptr, h,
                                     MROWS, DIM_, NA_, 0LL, 0);

    for (int i = 0; i < NIT_; i++) {
        // t = Asum[b] @ h[b] + h      (batched B via bStride; K=128)
        tgemm<<<grid, 256, SMEM_BYTES>>>(asum, h, nullptr, h, t,
                                         MROWS, DIM_, N_,
                                         (long long)N_ * DIM_, 0);
        // h = relu(t @ W_i + b_i)     (K=512)
        tgemm<<<grid, 256, SMEM_BYTES>>>(t, W_layers + (long long)i * DIM_ * DIM_,
                                         b_layers + i * DIM_, nullptr, h,
                                         MROWS, DIM_, DIM_, 0LL, 1);
    }

    finalize_kernel<<<B_, 256>>>(h, W_out, b_out, out);
}

// round 6
// speedup vs baseline: 1.9849x; 1.6585x over previous
#include <cuda_runtime.h>
#include <cuda_fp16.h>
#include <cstdint>

// Problem constants
#define B_    256
#define N_    128
#define EB_   5
#define NA_   64
#define DIM_  512
#define NIT_  3

// Scratch (static device globals)
__device__ float g_asumI[B_ * N_ * N_];                 // [B][128][128]  Σedges + I
__device__ float g_hT[B_ * DIM_ * N_];                  // [B][512][128]  hidden, transposed
__device__ float g_t [B_ * N_ * DIM_];                  // [B][128][512]  (I+A)h
__device__ float g_wT[NIT_ * DIM_ * DIM_ + DIM_ * NA_]; // transposed weights (+embed at end)

// ---------------------------------------------------------------------------
// Prep kernels
// ---------------------------------------------------------------------------
__global__ void asum_kernel(const float* __restrict__ adj) {
    int i = blockIdx.x * 256 + threadIdx.x;           // exact grid: B*N*N
    const float* p = adj + (long long)i * EB_;
    float s = p[1] + p[2] + p[3] + p[4];
    int nm = i & (N_ * N_ - 1);
    if ((nm >> 7) == (nm & 127)) s += 1.0f;           // + identity (folds residual)
    g_asumI[i] = s;
}

__global__ void transpose_kernel(const float* __restrict__ src, float* __restrict__ dst,
                                 int R, int C) {
    int i = blockIdx.x * 256 + threadIdx.x;
    if (i < R * C) { int r = i / C, c = i % C; dst[(long long)c * R + r] = src[i]; }
}

// ---------------------------------------------------------------------------
// FP16 split helpers
// ---------------------------------------------------------------------------
__device__ __forceinline__ void split_pair(float a0, float a1,
                                           uint32_t& hi, uint32_t& lo) {
    __half2 h = __floats2half2_rn(a0, a1);
    float2  f = __half22float2(h);
    __half2 l = __floats2half2_rn(a0 - f.x, a1 - f.y);
    hi = *reinterpret_cast<uint32_t*>(&h);
    lo = *reinterpret_cast<uint32_t*>(&l);
}

__device__ __forceinline__ void mma16816(float* c, const uint32_t* a, const uint32_t* b) {
    asm volatile(
        "mma.sync.aligned.m16n8k16.row.col.f32.f16.f16.f32 "
        "{%0,%1,%2,%3}, {%4,%5,%6,%7}, {%8,%9}, {%0,%1,%2,%3};"
        : "+f"(c[0]), "+f"(c[1]), "+f"(c[2]), "+f"(c[3])
        : "r"(a[0]), "r"(a[1]), "r"(a[2]), "r"(a[3]), "r"(b[0]), "r"(b[1]));
}

// ---------------------------------------------------------------------------
// 3xFP16-split tensor GEMM:  D[128,128] tile of  A[M,K] @ B[N,K]^T
//   (both operands K-major).  D = Ah*Bh + Ah*Bl + Al*Bh, fp32 accum.
//   B is pre-scaled by bScale at split time; epilogue multiplies by outScale.
//   bias: per D-row (length M) or null.  relu flag.
//   grid: (mtiles*ntiles, batch); aBS/bBS/dBS per-batch element strides.
// Smem: [2 buf][Ah,Al,Bh,Bl][k2=8][row 0..127] u32(half2), LDT=136 pad
//   -> fragment LDS conflict-free (k2 stride 136 ≡ 8 banks).
// ---------------------------------------------------------------------------
#define LDT 136

__global__ __launch_bounds__(256, 2)
void tgemm(const float* __restrict__ A, long long aBS,
           const float* __restrict__ Bm, long long bBS,
           float* __restrict__ D, long long dBS,
           const float* __restrict__ bias,
           int K, int Nglob, int ntiles, int relu,
           float bScale, float outScale)
{
    __shared__ uint32_t S[2][4][8][LDT];   // 34816 B

    const int tid  = threadIdx.x;
    const int lane = tid & 31;
    const int warp = tid >> 5;
    const int mtb  = blockIdx.x / ntiles;
    const int ntb  = blockIdx.x % ntiles;
    const int wm   = (warp >> 2) * 64;     // warp m-offset (0/64)
    const int wn   = (warp & 3) * 32;      // warp n-offset (0..96)

    const float* Ap = A  + aBS * blockIdx.y + (long long)mtb * 128 * K;
    const float* Bp = Bm + bBS * blockIdx.y + (long long)ntb * 128 * K;
    float*       Dp = D  + dBS * blockIdx.y + (long long)mtb * 128 * Nglob + ntb * 128;

    // loader mapping: row = tid>>1 (0..127), k2 base = (tid&1)*4  (k = k2*2..)
    const int lr  = tid >> 1;
    const int k2b = (tid & 1) * 4;
    const float* ag = Ap + (long long)lr * K + k2b * 2;
    const float* bg = Bp + (long long)lr * K + k2b * 2;

    float acc[4][4][4];
    #pragma unroll
    for (int i = 0; i < 4; i++)
        #pragma unroll
        for (int j = 0; j < 4; j++)
            #pragma unroll
            for (int q = 0; q < 4; q++) acc[i][j][q] = 0.0f;

    float aS[8], bS[8];
    *(float4*)&aS[0] = *(const float4*)(ag);
    *(float4*)&aS[4] = *(const float4*)(ag + 4);
    *(float4*)&bS[0] = *(const float4*)(bg);
    *(float4*)&bS[4] = *(const float4*)(bg + 4);

    const int C = K >> 4;
    int buf = 0;
    const int fr = lane >> 2;              // fragment row/col within 8
    const int fq = lane & 3;               // fragment k2 quad

    for (int c = 0; c < C; c++) {
        // split + store chunk c
        #pragma unroll
        for (int p = 0; p < 4; p++) {
            uint32_t hi, lo;
            split_pair(aS[2 * p], aS[2 * p + 1], hi, lo);
            S[buf][0][k2b + p][lr] = hi;
            S[buf][1][k2b + p][lr] = lo;
            split_pair(bS[2 * p] * bScale, bS[2 * p + 1] * bScale, hi, lo);
            S[buf][2][k2b + p][lr] = hi;
            S[buf][3][k2b + p][lr] = lo;
        }
        __syncthreads();

        // prefetch chunk c+1 (overlaps with compute)
        if (c + 1 < C) {
            *(float4*)&aS[0] = *(const float4*)(ag + (c + 1) * 16);
            *(float4*)&aS[4] = *(const float4*)(ag + (c + 1) * 16 + 4);
            *(float4*)&bS[0] = *(const float4*)(bg + (c + 1) * 16);
            *(float4*)&bS[4] = *(const float4*)(bg + (c + 1) * 16 + 4);
        }

        const uint32_t (*SAh)[LDT] = S[buf][0];
        const uint32_t (*SAl)[LDT] = S[buf][1];
        const uint32_t (*SBh)[LDT] = S[buf][2];
        const uint32_t (*SBl)[LDT] = S[buf][3];

        uint32_t af[4][4], bf[4][2];
        #pragma unroll
        for (int mt = 0; mt < 4; mt++) {
            const int m0 = wm + mt * 16 + fr;
            af[mt][0] = SAh[fq][m0];
            af[mt][1] = SAh[fq][m0 + 8];
            af[mt][2] = SAh[fq + 4][m0];
            af[mt][3] = SAh[fq + 4][m0 + 8];
        }
        #pragma unroll
        for (int nt = 0; nt < 4; nt++) {
            const int n0 = wn + nt * 8 + fr;
            bf[nt][0] = SBh[fq][n0];
            bf[nt][1] = SBh[fq + 4][n0];
        }
        // term 1: Ah * Bh
        #pragma unroll
        for (int mt = 0; mt < 4; mt++)
            #pragma unroll
            for (int nt = 0; nt < 4; nt++) mma16816(acc[mt][nt], af[mt], bf[nt]);
        // term 2: Ah * Bl
        #pragma unroll
        for (int nt = 0; nt < 4; nt++) {
            const int n0 = wn + nt * 8 + fr;
            bf[nt][0] = SBl[fq][n0];
            bf[nt][1] = SBl[fq + 4][n0];
        }
        #pragma unroll
        for (int mt = 0; mt < 4; mt++)
            #pragma unroll
            for (int nt = 0; nt < 4; nt++) mma16816(acc[mt][nt], af[mt], bf[nt]);
        // term 3: Al * Bh
        #pragma unroll
        for (int mt = 0; mt < 4; mt++) {
            const int m0 = wm + mt * 16 + fr;
            af[mt][0] = SAl[fq][m0];
            af[mt][1] = SAl[fq][m0 + 8];
            af[mt][2] = SAl[fq + 4][m0];
            af[mt][3] = SAl[fq + 4][m0 + 8];
        }
        #pragma unroll
        for (int nt = 0; nt < 4; nt++) {
            const int n0 = wn + nt * 8 + fr;
            bf[nt][0] = SBh[fq][n0];
            bf[nt][1] = SBh[fq + 4][n0];
        }
        #pragma unroll
        for (int mt = 0; mt < 4; mt++)
            #pragma unroll
            for (int nt = 0; nt < 4; nt++) mma16816(acc[mt][nt], af[mt], bf[nt]);

        buf ^= 1;
    }

    // --- epilogue ---
    // frag map: c0:(r,c) c1:(r,c+1) c2:(r+8,c) c3:(r+8,c+1)
    //   r = wm + mt*16 + lane/4,  c = wn + nt*8 + 2*(lane&3)
    #pragma unroll
    for (int mt = 0; mt < 4; mt++) {
        const int rr0 = wm + mt * 16 + fr;
        const int rr1 = rr0 + 8;
        const float bv0 = bias ? bias[mtb * 128 + rr0] : 0.0f;
        const float bv1 = bias ? bias[mtb * 128 + rr1] : 0.0f;
        #pragma unroll
        for (int nt = 0; nt < 4; nt++) {
            const int cc = wn + nt * 8 + 2 * (lane & 3);
            float v0 = acc[mt][nt][0] * outScale + bv0;
            float v1 = acc[mt][nt][1] * outScale + bv0;
            float v2 = acc[mt][nt][2] * outScale + bv1;
            float v3 = acc[mt][nt][3] * outScale + bv1;
            if (relu) {
                v0 = fmaxf(v0, 0.0f); v1 = fmaxf(v1, 0.0f);
                v2 = fmaxf(v2, 0.0f); v3 = fmaxf(v3, 0.0f);
            }
            *(float2*)(Dp + (long long)rr0 * Nglob + cc) = make_float2(v0, v1);
            *(float2*)(Dp + (long long)rr1 * Nglob + cc) = make_float2(v2, v3);
        }
    }
}

// ---------------------------------------------------------------------------
// finalize: graph_repr[b] = mean_n hT[b][d][n];  logit = repr @ W_out + b_out
// out = [ logit(256) | graph_repr(256*512) ]
// ---------------------------------------------------------------------------
__global__ void finalize_kernel(const float* __restrict__ hT,
                                const float* __restrict__ W_out,
                                const float* __restrict__ b_out,
                                float* __restrict__ out)
{
    const int b = blockIdx.x, tid = threadIdx.x;
    const float* base = hT + (long long)b * DIM_ * N_;
    const float4* r0 = (const float4*)(base + (long long)tid * N_);
    const float4* r1 = (const float4*)(base + (long long)(tid + 256) * N_);
    float s0 = 0.0f, s1 = 0.0f;
    #pragma unroll 8
    for (int j = 0; j < 32; j++) {
        float4 a = r0[j]; s0 += (a.x + a.y) + (a.z + a.w);
        float4 c = r1[j]; s1 += (c.x + c.y) + (c.z + c.w);
    }
    const float g0 = s0 * (1.0f / (float)N_);
    const float g1 = s1 * (1.0f / (float)N_);
    out[B_ + b * DIM_ + tid]       = g0;
    out[B_ + b * DIM_ + tid + 256] = g1;

    __shared__ float red[256];
    red[tid] = g0 * W_out[tid] + g1 * W_out[tid + 256];
    __syncthreads();
    for (int s = 128; s > 0; s >>= 1) {
        if (tid < s) red[tid] += red[tid + s];
        __syncthreads();
    }
    if (tid == 0) out[b] = red[0] + b_out[0];
}

// ---------------------------------------------------------------------------
// launch
// ---------------------------------------------------------------------------
extern "C" void kernel_launch(void* const* d_in, const int* in_sizes, int n_in,
                              void* d_out, int out_size)
{
    const float* adj      = (const float*)d_in[0];
    // d_in[1] = hidden (unused by forward)
    const float* node     = (const float*)d_in[2];
    const float* W_embed  = (const float*)d_in[3];
    const float* b_embed  = (const float*)d_in[4];
    const float* W_layers = (const float*)d_in[5];
    const float* b_layers = (const float*)d_in[6];
    const float* W_out    = (const float*)d_in[7];
    const float* b_out    = (const float*)d_in[8];
    float* out = (float*)d_out;

    float *asumI, *hT, *t, *wT;
    cudaGetSymbolAddress((void**)&asumI, g_asumI);
    cudaGetSymbolAddress((void**)&hT,    g_hT);
    cudaGetSymbolAddress((void**)&t,     g_t);
    cudaGetSymbolAddress((void**)&wT,    g_wT);

    // prep: folded adjacency (+I) and one-time weight transposes
    asum_kernel<<<(B_ * N_ * N_) / 256, 256>>>(adj);
    for (int i = 0; i < NIT_; i++)
        transpose_kernel<<<(DIM_ * DIM_ + 255) / 256, 256>>>(
            W_layers + (long long)i * DIM_ * DIM_, wT + (long long)i * DIM_ * DIM_,
            DIM_, DIM_);
    transpose_kernel<<<(NA_ * DIM_ + 255) / 256, 256>>>(
        W_embed, wT + (long long)NIT_ * DIM_ * DIM_, NA_, DIM_);

    dim3 grid(4, B_);
    const float S  = 1.0f / 64.0f;   // B-operand pre-scale (fp16 range safety)
    const float iS = 64.0f;

    // embed: hT[b] = WembT[512x64] @ node[b][128x64]^T + b_embed  (K=64)
    tgemm<<<grid, 256>>>(
        wT + (long long)NIT_ * DIM_ * DIM_, 0LL,
        node, (long long)N_ * NA_,
        hT, (long long)DIM_ * N_,
        b_embed, NA_, N_, /*ntiles=*/1, /*relu=*/0, 1.0f, 1.0f);

    for (int i = 0; i < NIT_; i++) {
        // t[b][128x512] = asumI[b][128x128] @ hT[b][512x128]^T   (K=128)
        tgemm<<<grid, 256>>>(
            asumI, (long long)N_ * N_,
            hT, (long long)DIM_ * N_,
            t, (long long)N_ * DIM_,
            nullptr, N_, DIM_, /*ntiles=*/4, /*relu=*/0, S, iS);
        // hT[b][512x128] = relu(WT_i[512x512] @ t[b][128x512]^T + b_i)  (K=512)
        tgemm<<<grid, 256>>>(
            wT + (long long)i * DIM_ * DIM_, 0LL,
            t, (long long)N_ * DIM_,
            hT, (long long)DIM_ * N_,
            b_layers + i * DIM_, DIM_, N_, /*ntiles=*/1, /*relu=*/1, S, iS);
    }

    finalize_kernel<<<B_, 256>>>(hT, W_out, b_out, out);
}